// round 8
// baseline (speedup 1.0000x reference)
#include <cuda_runtime.h>

#define B_ 32
#define L_ 4096
#define H_ 1024

#define GSPLIT 64                 // g-chunks for split-K projection
#define GCH    (H_ / GSPLIT)      // 16 g per chunk
#define BSPLIT 2                  // b-halves
#define BCH    (B_ / BSPLIT)      // 16 b per block

// Scratch
__device__ float g_vp[GSPLIT * B_ * H_];   // 8 MB split-K partials
__device__ float g_v[B_ * H_];             // projected hidden
__device__ int   g_cnt[B_];                // arrival counters (zero-init,
                                           // self-resetting -> replay-safe)

// ---------------------------------------------------------------------------
// Kernel A1: split-K partial projection, split over g AND b.
//   vp[gc, b, h] = sum_{g in chunk gc} hid[b,g] * W[g,h]
// Grid (8, 64, 2) = 1024 blocks x 128 thr. 16 accumulators/thread (~60 regs)
// -> 4x the warp occupancy of the previous 32-acc version. W is read twice
// (once per b-half) = 8 MB, still ~1 us of DRAM.
// ---------------------------------------------------------------------------
__global__ void proj_partial(const float* __restrict__ hid,
                             const float* __restrict__ W) {
    const int h  = blockIdx.x * 128 + threadIdx.x;
    const int gc = blockIdx.y;
    const int bh = blockIdx.z;                 // b-half

    __shared__ float sh[BCH][GCH];             // 1 KB
    for (int i = threadIdx.x; i < BCH * GCH; i += 128) {
        const int b = i / GCH, g = i % GCH;
        sh[b][g] = hid[(bh * BCH + b) * H_ + gc * GCH + g];
    }
    __syncthreads();

    float acc[BCH];
#pragma unroll
    for (int b = 0; b < BCH; ++b) acc[b] = 0.f;

    const float* __restrict__ Wp = W + (size_t)(gc * GCH) * H_ + h;
#pragma unroll
    for (int g = 0; g < GCH; ++g) {
        const float w = Wp[(size_t)g * H_];    // coalesced
#pragma unroll
        for (int b = 0; b < BCH; ++b)
            acc[b] = fmaf(sh[b][g], w, acc[b]);
    }

    float* __restrict__ outp =
        g_vp + ((size_t)gc * B_ + bh * BCH) * H_ + h;
#pragma unroll
    for (int b = 0; b < BCH; ++b) outp[(size_t)b * H_] = acc[b];
}

// ---------------------------------------------------------------------------
// Kernel A2: reduce partials (L2-hot, 8 MB). v[i] = sum_gc vp[gc, i].
// ---------------------------------------------------------------------------
__global__ void proj_reduce() {
    const int i = blockIdx.x * 256 + threadIdx.x;   // 0 .. B*H-1
    float s = 0.f;
#pragma unroll
    for (int c = 0; c < GSPLIT; ++c)
        s += g_vp[(size_t)c * (B_ * H_) + i];
    g_v[i] = s;
}

// ---------------------------------------------------------------------------
// Kernel B: energies + fused softmax epilogue (unchanged from R5; sits at
// the LTS ceiling ~6.4 TB/s on the 512 MiB enc stream).
// ---------------------------------------------------------------------------
__global__ void energies_softmax(const float* __restrict__ enc,
                                 float* __restrict__ out) {
    const int b    = blockIdx.y;
    const int tid  = threadIdx.x;
    const int warp = tid >> 5;
    const int lane = tid & 31;

    __shared__ float4 sv[H_ / 4];   // 4 KB: v[b]
    __shared__ float  red[16];
    __shared__ int    s_last;

    {
        const float4* __restrict__ v4 = (const float4*)(g_v + b * H_);
        for (int i = tid; i < H_ / 4; i += 512) sv[i] = v4[i];
    }
    __syncthreads();

    const int l0 = (blockIdx.x * 16 + warp) * 4;     // 4 rows per warp
    const float4* __restrict__ base =
        (const float4*)(enc + ((size_t)l0 * B_ + b) * (size_t)H_);
    const size_t row4 = (size_t)B_ * H_ / 4;

    float s[4] = {0.f, 0.f, 0.f, 0.f};
#pragma unroll
    for (int i = 0; i < 8; ++i) {
        const float4 vv = sv[i * 32 + lane];
#pragma unroll
        for (int j = 0; j < 4; ++j) {
            float4 e = base[(size_t)j * row4 + i * 32 + lane];
            s[j] = fmaf(vv.x, e.x, s[j]);
            s[j] = fmaf(vv.y, e.y, s[j]);
            s[j] = fmaf(vv.z, e.z, s[j]);
            s[j] = fmaf(vv.w, e.w, s[j]);
        }
    }

#pragma unroll
    for (int j = 0; j < 4; ++j) {
        float t = s[j];
#pragma unroll
        for (int o = 16; o; o >>= 1)
            t += __shfl_down_sync(0xffffffffu, t, o);
        if (lane == 0) out[b * L_ + l0 + j] = t;
    }

    // ---- arrival: is this the last block for row b? ----
    __threadfence();
    __syncthreads();
    if (tid == 0) {
        const int old = atomicAdd(&g_cnt[b], 1);
        s_last = (old == gridDim.x - 1);
    }
    __syncthreads();
    if (!s_last) return;

    // ---- softmax epilogue on L2-hot row (one block per b) ----
    float4* __restrict__ o4 = (float4*)(out + b * L_);   // 1024 float4
    float4 x0 = o4[tid];
    float4 x1 = o4[tid + 512];

    float m = fmaxf(fmaxf(fmaxf(x0.x, x0.y), fmaxf(x0.z, x0.w)),
                    fmaxf(fmaxf(x1.x, x1.y), fmaxf(x1.z, x1.w)));
#pragma unroll
    for (int o = 16; o; o >>= 1) m = fmaxf(m, __shfl_xor_sync(0xffffffffu, m, o));
    if (lane == 0) red[warp] = m;
    __syncthreads();
    if (tid < 32) {
        float t = (lane < 16) ? red[lane] : -1e30f;
#pragma unroll
        for (int o = 8; o; o >>= 1) t = fmaxf(t, __shfl_xor_sync(0xffffffffu, t, o));
        red[lane & 15] = t;
    }
    __syncthreads();
    m = red[0];

    x0.x = __expf(x0.x - m); x0.y = __expf(x0.y - m);
    x0.z = __expf(x0.z - m); x0.w = __expf(x0.w - m);
    x1.x = __expf(x1.x - m); x1.y = __expf(x1.y - m);
    x1.z = __expf(x1.z - m); x1.w = __expf(x1.w - m);
    float sum = ((x0.x + x0.y) + (x0.z + x0.w)) +
                ((x1.x + x1.y) + (x1.z + x1.w));
#pragma unroll
    for (int o = 16; o; o >>= 1) sum += __shfl_xor_sync(0xffffffffu, sum, o);
    __syncthreads();
    if (lane == 0) red[warp] = sum;
    __syncthreads();
    if (tid < 32) {
        float t = (lane < 16) ? red[lane] : 0.f;
#pragma unroll
        for (int o = 8; o; o >>= 1) t += __shfl_xor_sync(0xffffffffu, t, o);
        red[lane & 15] = t;
    }
    __syncthreads();
    const float inv = 1.f / red[0];

    x0.x *= inv; x0.y *= inv; x0.z *= inv; x0.w *= inv;
    x1.x *= inv; x1.y *= inv; x1.z *= inv; x1.w *= inv;
    o4[tid]       = x0;
    o4[tid + 512] = x1;

    if (tid == 0) g_cnt[b] = 0;      // self-reset for next replay
}

// ---------------------------------------------------------------------------
extern "C" void kernel_launch(void* const* d_in, const int* in_sizes, int n_in,
                              void* d_out, int out_size) {
    const float* hid = (const float*)d_in[0];   // [1,B,H]
    const float* enc = (const float*)d_in[1];   // [L,B,H]
    const float* W   = (const float*)d_in[2];   // [H,H]
    // d_in[3] = bias: irrelevant (softmax shift invariance)
    float* out = (float*)d_out;                 // [B,1,L]

    proj_partial    <<<dim3(H_ / 128, GSPLIT, BSPLIT), 128>>>(hid, W);
    proj_reduce     <<<B_ * H_ / 256, 256>>>();
    energies_softmax<<<dim3(L_ / 64, B_), 512>>>(enc, out);
}

// round 10
// speedup vs baseline: 1.0460x; 1.0460x over previous
#include <cuda_runtime.h>

#define B_ 32
#define L_ 4096
#define H_ 1024

#define GSPLIT 64                 // g-chunks for split-K projection
#define GCH    (H_ / GSPLIT)      // 16 g per chunk
#define BSPLIT 4                  // b-quarters
#define BCH    (B_ / BSPLIT)      // 8 b per block

// Scratch
__device__ float g_vp[GSPLIT * B_ * H_];   // 8 MB split-K partials
__device__ float g_v[B_ * H_];             // projected hidden
__device__ int   g_cnt[B_];                // arrival counters (zero-init,
                                           // self-resetting -> replay-safe)

// ---------------------------------------------------------------------------
// Kernel A1: split-K partial projection, split over g AND b.
//   vp[gc, b, h] = sum_{g in chunk gc} hid[b,g] * W[g,h]
// Grid (8, 64, 4) = 2048 blocks x 128 thr. 8 accumulators/thread (~50 regs)
// -> ~2x the occupancy of the BCH=16 version. W read 4x = 16 MB (~2.5 us).
// ---------------------------------------------------------------------------
__global__ void proj_partial(const float* __restrict__ hid,
                             const float* __restrict__ W) {
    const int h  = blockIdx.x * 128 + threadIdx.x;
    const int gc = blockIdx.y;
    const int bq = blockIdx.z;                 // b-quarter

    __shared__ float sh[BCH][GCH];             // 512 B
    for (int i = threadIdx.x; i < BCH * GCH; i += 128) {
        const int b = i / GCH, g = i % GCH;
        sh[b][g] = hid[(bq * BCH + b) * H_ + gc * GCH + g];
    }
    __syncthreads();

    float acc[BCH];
#pragma unroll
    for (int b = 0; b < BCH; ++b) acc[b] = 0.f;

    const float* __restrict__ Wp = W + (size_t)(gc * GCH) * H_ + h;
#pragma unroll
    for (int g = 0; g < GCH; ++g) {
        const float w = Wp[(size_t)g * H_];    // coalesced
#pragma unroll
        for (int b = 0; b < BCH; ++b)
            acc[b] = fmaf(sh[b][g], w, acc[b]);
    }

    float* __restrict__ outp =
        g_vp + ((size_t)gc * B_ + bq * BCH) * H_ + h;
#pragma unroll
    for (int b = 0; b < BCH; ++b) outp[(size_t)b * H_] = acc[b];
}

// ---------------------------------------------------------------------------
// Kernel A2: reduce partials (L2-hot, 8 MB). v[i] = sum_gc vp[gc, i].
// 256 blocks x 128 threads; 64 independent loads per thread.
// ---------------------------------------------------------------------------
__global__ void proj_reduce() {
    const int i = blockIdx.x * 128 + threadIdx.x;   // 0 .. B*H-1
    float s = 0.f;
#pragma unroll
    for (int c = 0; c < GSPLIT; ++c)
        s += g_vp[(size_t)c * (B_ * H_) + i];
    g_v[i] = s;
}

// ---------------------------------------------------------------------------
// Kernel B: energies + fused softmax epilogue.
// enc loads use __ldcs (read-once stream, evict-first) to keep L2 clean.
// ---------------------------------------------------------------------------
__global__ void energies_softmax(const float* __restrict__ enc,
                                 float* __restrict__ out) {
    const int b    = blockIdx.y;
    const int tid  = threadIdx.x;
    const int warp = tid >> 5;
    const int lane = tid & 31;

    __shared__ float4 sv[H_ / 4];   // 4 KB: v[b]
    __shared__ float  red[16];
    __shared__ int    s_last;

    {
        const float4* __restrict__ v4 = (const float4*)(g_v + b * H_);
        for (int i = tid; i < H_ / 4; i += 512) sv[i] = v4[i];
    }
    __syncthreads();

    const int l0 = (blockIdx.x * 16 + warp) * 4;     // 4 rows per warp
    const float4* __restrict__ base =
        (const float4*)(enc + ((size_t)l0 * B_ + b) * (size_t)H_);
    const size_t row4 = (size_t)B_ * H_ / 4;

    float s[4] = {0.f, 0.f, 0.f, 0.f};
#pragma unroll
    for (int i = 0; i < 8; ++i) {
        const float4 vv = sv[i * 32 + lane];
#pragma unroll
        for (int j = 0; j < 4; ++j) {
            float4 e = __ldcs(&base[(size_t)j * row4 + i * 32 + lane]);
            s[j] = fmaf(vv.x, e.x, s[j]);
            s[j] = fmaf(vv.y, e.y, s[j]);
            s[j] = fmaf(vv.z, e.z, s[j]);
            s[j] = fmaf(vv.w, e.w, s[j]);
        }
    }

#pragma unroll
    for (int j = 0; j < 4; ++j) {
        float t = s[j];
#pragma unroll
        for (int o = 16; o; o >>= 1)
            t += __shfl_down_sync(0xffffffffu, t, o);
        if (lane == 0) out[b * L_ + l0 + j] = t;
    }

    // ---- arrival: is this the last block for row b? ----
    __threadfence();
    __syncthreads();
    if (tid == 0) {
        const int old = atomicAdd(&g_cnt[b], 1);
        s_last = (old == gridDim.x - 1);
    }
    __syncthreads();
    if (!s_last) return;

    // ---- softmax epilogue on L2-hot row (one block per b) ----
    float4* __restrict__ o4 = (float4*)(out + b * L_);   // 1024 float4
    float4 x0 = o4[tid];
    float4 x1 = o4[tid + 512];

    float m = fmaxf(fmaxf(fmaxf(x0.x, x0.y), fmaxf(x0.z, x0.w)),
                    fmaxf(fmaxf(x1.x, x1.y), fmaxf(x1.z, x1.w)));
#pragma unroll
    for (int o = 16; o; o >>= 1) m = fmaxf(m, __shfl_xor_sync(0xffffffffu, m, o));
    if (lane == 0) red[warp] = m;
    __syncthreads();
    if (tid < 32) {
        float t = (lane < 16) ? red[lane] : -1e30f;
#pragma unroll
        for (int o = 8; o; o >>= 1) t = fmaxf(t, __shfl_xor_sync(0xffffffffu, t, o));
        red[lane & 15] = t;
    }
    __syncthreads();
    m = red[0];

    x0.x = __expf(x0.x - m); x0.y = __expf(x0.y - m);
    x0.z = __expf(x0.z - m); x0.w = __expf(x0.w - m);
    x1.x = __expf(x1.x - m); x1.y = __expf(x1.y - m);
    x1.z = __expf(x1.z - m); x1.w = __expf(x1.w - m);
    float sum = ((x0.x + x0.y) + (x0.z + x0.w)) +
                ((x1.x + x1.y) + (x1.z + x1.w));
#pragma unroll
    for (int o = 16; o; o >>= 1) sum += __shfl_xor_sync(0xffffffffu, sum, o);
    __syncthreads();
    if (lane == 0) red[warp] = sum;
    __syncthreads();
    if (tid < 32) {
        float t = (lane < 16) ? red[lane] : 0.f;
#pragma unroll
        for (int o = 8; o; o >>= 1) t += __shfl_xor_sync(0xffffffffu, t, o);
        red[lane & 15] = t;
    }
    __syncthreads();
    const float inv = 1.f / red[0];

    x0.x *= inv; x0.y *= inv; x0.z *= inv; x0.w *= inv;
    x1.x *= inv; x1.y *= inv; x1.z *= inv; x1.w *= inv;
    o4[tid]       = x0;
    o4[tid + 512] = x1;

    if (tid == 0) g_cnt[b] = 0;      // self-reset for next replay
}

// ---------------------------------------------------------------------------
extern "C" void kernel_launch(void* const* d_in, const int* in_sizes, int n_in,
                              void* d_out, int out_size) {
    const float* hid = (const float*)d_in[0];   // [1,B,H]
    const float* enc = (const float*)d_in[1];   // [L,B,H]
    const float* W   = (const float*)d_in[2];   // [H,H]
    // d_in[3] = bias: irrelevant (softmax shift invariance)
    float* out = (float*)d_out;                 // [B,1,L]

    proj_partial    <<<dim3(H_ / 128, GSPLIT, BSPLIT), 128>>>(hid, W);
    proj_reduce     <<<B_ * H_ / 128, 128>>>();
    energies_softmax<<<dim3(L_ / 64, B_), 512>>>(enc, out);
}